// round 9
// baseline (speedup 1.0000x reference)
#include <cuda_runtime.h>

// Elementwise LSTM-cell update (the RGCN convs are identity on node features):
//   S = X + H; g = sigmoid(S); t = tanh(S)
//   C_new = g*C + g*t
//   H_new = g * tanh(C_new)
// Outputs: d_out[0 .. n)   = H_new
//          d_out[n .. 2n)  = C_new
//
// Pure HBM-bound: 3 reads + 2 writes of 204.8MB each => ~1.02 GB traffic.

__device__ __forceinline__ float sigm_f(float s) {
    // accurate fast sigmoid: 1/(1+exp(-s)); __expf ~2-ulp for moderate |s|
    return 1.0f / (1.0f + __expf(-s));
}

__device__ __forceinline__ float tanh_f(float s) {
    // tanh(s) = 1 - 2/(exp(2s)+1); saturates correctly as exp -> inf/0
    return 1.0f - 2.0f / (__expf(2.0f * s) + 1.0f);
}

__device__ __forceinline__ void cell(float x, float h, float c,
                                     float& hn, float& cn) {
    float s = x + h;
    float g = sigm_f(s);      // I == F == O (identical pre-activation)
    float t = tanh_f(s);
    float cnew = g * c + g * t;
    cn = cnew;
    hn = g * tanh_f(cnew);
}

static constexpr int TPB = 256;
static constexpr int VPT = 4;   // float4 chunks per thread (front-batched for MLP)

__global__ __launch_bounds__(TPB)
void rrgcn_lstm_kernel(const float4* __restrict__ X,
                       const float4* __restrict__ H,
                       const float4* __restrict__ C,
                       float4* __restrict__ Hn,
                       float4* __restrict__ Cn,
                       int n4) {
    const int total = gridDim.x * blockDim.x;
    const int base  = blockIdx.x * blockDim.x + threadIdx.x;

    int  idx[VPT];
    float4 xv[VPT], hv[VPT], cv[VPT];
    bool ok[VPT];

    // Front-batch all loads (12 independent LDG.128) to maximize MLP.
#pragma unroll
    for (int j = 0; j < VPT; j++) {
        idx[j] = base + j * total;
        ok[j]  = idx[j] < n4;
        if (ok[j]) {
            xv[j] = X[idx[j]];
            hv[j] = H[idx[j]];
            cv[j] = C[idx[j]];
        }
    }

#pragma unroll
    for (int j = 0; j < VPT; j++) {
        if (!ok[j]) continue;
        float4 hn, cn;
        cell(xv[j].x, hv[j].x, cv[j].x, hn.x, cn.x);
        cell(xv[j].y, hv[j].y, cv[j].y, hn.y, cn.y);
        cell(xv[j].z, hv[j].z, cv[j].z, hn.z, cn.z);
        cell(xv[j].w, hv[j].w, cv[j].w, hn.w, cn.w);
        Hn[idx[j]] = hn;
        Cn[idx[j]] = cn;
    }
}

extern "C" void kernel_launch(void* const* d_in, const int* in_sizes, int n_in,
                              void* d_out, int out_size) {
    // metadata order: X, edge_attr, global_attr, H, C
    const float* X = (const float*)d_in[0];
    const float* H = (const float*)d_in[3];
    const float* C = (const float*)d_in[4];
    float* out = (float*)d_out;

    const int n  = in_sizes[0];          // 200000*256 = 51,200,000 (divisible by 4)
    const int n4 = n / 4;                // 12,800,000 float4

    float* Hn = out;                     // first half: H_new
    float* Cn = out + n;                 // second half: C_new

    const long long threads_needed = (n4 + VPT - 1) / VPT;
    int blocks = (int)((threads_needed + TPB - 1) / TPB);

    rrgcn_lstm_kernel<<<blocks, TPB>>>(
        (const float4*)X, (const float4*)H, (const float4*)C,
        (float4*)Hn, (float4*)Cn, n4);
}

// round 10
// speedup vs baseline: 1.0148x; 1.0148x over previous
#include <cuda_runtime.h>

// Elementwise LSTM-cell update (RGCN convs are identity on node features):
//   S = X + H; g = sigmoid(S); t = tanh(S)
//   C_new = g*C + g*t
//   H_new = g * tanh(C_new)
// Outputs: d_out[0 .. n) = H_new, d_out[n .. 2n) = C_new
//
// HBM-bound: 3 reads + 2 writes x 204.8MB = 1.024 GB fixed traffic.
// R9 change vs R8: VPT 4->2 (regs 64->~40, occupancy 45%->~75%) and
// streaming cache hints (__ldcs/__stcs) since every byte is single-touch.

__device__ __forceinline__ float sigm_f(float s) {
    return 1.0f / (1.0f + __expf(-s));
}

__device__ __forceinline__ float tanh_f(float s) {
    return 1.0f - 2.0f / (__expf(2.0f * s) + 1.0f);
}

__device__ __forceinline__ void cell(float x, float h, float c,
                                     float& hn, float& cn) {
    float s = x + h;
    float g = sigm_f(s);      // I == F == O (identical pre-activation)
    float t = tanh_f(s);
    float cnew = g * c + g * t;
    cn = cnew;
    hn = g * tanh_f(cnew);
}

static constexpr int TPB = 256;
static constexpr int VPT = 2;   // float4 chunks per thread

__device__ __forceinline__ float4 ldcs4(const float4* p) {
    return __ldcs(p);
}

__global__ __launch_bounds__(TPB)
void rrgcn_lstm_kernel(const float4* __restrict__ X,
                       const float4* __restrict__ H,
                       const float4* __restrict__ C,
                       float4* __restrict__ Hn,
                       float4* __restrict__ Cn,
                       int n4) {
    const int total = gridDim.x * blockDim.x;
    const int base  = blockIdx.x * blockDim.x + threadIdx.x;

    int  idx[VPT];
    float4 xv[VPT], hv[VPT], cv[VPT];
    bool ok[VPT];

    // Front-batch all loads (6 independent LDG.128.CS).
#pragma unroll
    for (int j = 0; j < VPT; j++) {
        idx[j] = base + j * total;
        ok[j]  = idx[j] < n4;
        if (ok[j]) {
            xv[j] = ldcs4(X + idx[j]);
            hv[j] = ldcs4(H + idx[j]);
            cv[j] = ldcs4(C + idx[j]);
        }
    }

#pragma unroll
    for (int j = 0; j < VPT; j++) {
        if (!ok[j]) continue;
        float4 hn, cn;
        cell(xv[j].x, hv[j].x, cv[j].x, hn.x, cn.x);
        cell(xv[j].y, hv[j].y, cv[j].y, hn.y, cn.y);
        cell(xv[j].z, hv[j].z, cv[j].z, hn.z, cn.z);
        cell(xv[j].w, hv[j].w, cv[j].w, hn.w, cn.w);
        __stcs(Hn + idx[j], hn);
        __stcs(Cn + idx[j], cn);
    }
}

extern "C" void kernel_launch(void* const* d_in, const int* in_sizes, int n_in,
                              void* d_out, int out_size) {
    // metadata order: X, edge_attr, global_attr, H, C
    const float* X = (const float*)d_in[0];
    const float* H = (const float*)d_in[3];
    const float* C = (const float*)d_in[4];
    float* out = (float*)d_out;

    const int n  = in_sizes[0];          // 51,200,000
    const int n4 = n / 4;                // 12,800,000 float4

    float* Hn = out;                     // first half: H_new
    float* Cn = out + n;                 // second half: C_new

    const long long threads_needed = (n4 + VPT - 1) / VPT;
    int blocks = (int)((threads_needed + TPB - 1) / TPB);   // 25000

    rrgcn_lstm_kernel<<<blocks, TPB>>>(
        (const float4*)X, (const float4*)H, (const float4*)C,
        (float4*)Hn, (float4*)Cn, n4);
}

// round 11
// speedup vs baseline: 1.0273x; 1.0123x over previous
#include <cuda_runtime.h>

// Elementwise LSTM-cell update (RGCN convs are identity on node features):
//   S = X + H; g = sigmoid(S); t = tanh(S)
//   C_new = g*C + g*t
//   H_new = g * tanh(C_new)
// Outputs: d_out[0 .. n) = H_new, d_out[n .. 2n) = C_new
//
// HBM-bound: 3 reads + 2 writes x 204.8MB = 1.024 GB fixed traffic.
// R10 change vs R9: VPT 2->1 with __launch_bounds__(256, 8) to force
// regs<=32 -> 8 CTAs/SM -> 100% theoretical occupancy. More eligible
// warps to cover DRAM latency (issue% was 58.7 at occ 64.6).

__device__ __forceinline__ float sigm_f(float s) {
    return 1.0f / (1.0f + __expf(-s));
}

__device__ __forceinline__ float tanh_f(float s) {
    return 1.0f - 2.0f / (__expf(2.0f * s) + 1.0f);
}

__device__ __forceinline__ void cell(float x, float h, float c,
                                     float& hn, float& cn) {
    float s = x + h;
    float g = sigm_f(s);      // I == F == O (identical pre-activation)
    float t = tanh_f(s);
    float cnew = g * c + g * t;
    cn = cnew;
    hn = g * tanh_f(cnew);
}

static constexpr int TPB = 256;

__global__ __launch_bounds__(TPB, 8)
void rrgcn_lstm_kernel(const float4* __restrict__ X,
                       const float4* __restrict__ H,
                       const float4* __restrict__ C,
                       float4* __restrict__ Hn,
                       float4* __restrict__ Cn,
                       int n4) {
    const int idx = blockIdx.x * TPB + threadIdx.x;
    if (idx >= n4) return;   // never taken at n4=12.8M, grid=50000 (exact cover)

    const float4 xv = __ldcs(X + idx);
    const float4 hv = __ldcs(H + idx);
    const float4 cv = __ldcs(C + idx);

    float4 hn, cn;
    cell(xv.x, hv.x, cv.x, hn.x, cn.x);
    cell(xv.y, hv.y, cv.y, hn.y, cn.y);
    cell(xv.z, hv.z, cv.z, hn.z, cn.z);
    cell(xv.w, hv.w, cv.w, hn.w, cn.w);

    __stcs(Hn + idx, hn);
    __stcs(Cn + idx, cn);
}

extern "C" void kernel_launch(void* const* d_in, const int* in_sizes, int n_in,
                              void* d_out, int out_size) {
    // metadata order: X, edge_attr, global_attr, H, C
    const float* X = (const float*)d_in[0];
    const float* H = (const float*)d_in[3];
    const float* C = (const float*)d_in[4];
    float* out = (float*)d_out;

    const int n  = in_sizes[0];          // 51,200,000
    const int n4 = n / 4;                // 12,800,000 float4

    float* Hn = out;                     // first half: H_new
    float* Cn = out + n;                 // second half: C_new

    const int blocks = (n4 + TPB - 1) / TPB;   // 50000

    rrgcn_lstm_kernel<<<blocks, TPB>>>(
        (const float4*)X, (const float4*)H, (const float4*)C,
        (float4*)Hn, (float4*)Cn, n4);
}